// round 16
// baseline (speedup 1.0000x reference)
#include <cuda_runtime.h>
#include <cuda_fp16.h>
#include <cstdint>
#include <cstddef>

#define NSRC 4096
#define NTGT 4096
#define DIM  1024

// ---------------- scratch (__device__ globals; no allocations allowed) -----
__device__ float g_sqs[NSRC];
__device__ float g_sqt[NTGT];
__device__ float g_sbavg[1];
__device__ float g_sqpart_s[(size_t)NSRC * (DIM / 32)];
__device__ float g_sqpart_t[(size_t)NTGT * (DIM / 32)];
__device__ float g_krspart[(size_t)NSRC * (NTGT / 32)];

__device__ __half g_srch[(size_t)NSRC * DIM];
__device__ __half g_tgth[(size_t)NTGT * DIM];
__device__ __half g_Wsh[(size_t)DIM * DIM];
__device__ __half g_Wth[(size_t)DIM * DIM];
__device__ __half g_sph[(size_t)NSRC * DIM];
__device__ __half g_tph[(size_t)NTGT * DIM];
__device__ __half g_tTh[(size_t)DIM * NTGT];
__device__ __half g_Kh[(size_t)NSRC * NTGT];    // row-prescaled fp16 K (S_r cancels)

// ---------------- helpers ----------------------------------------------------
__device__ __forceinline__ uint32_t smem_to_u32(const void* p) {
    uint32_t a;
    asm("{ .reg .u64 t; cvta.to.shared.u64 t, %1; cvt.u32.u64 %0, t; }" : "=r"(a) : "l"(p));
    return a;
}
__device__ __forceinline__ void cp_async16(uint32_t dst, const void* src) {
    asm volatile("cp.async.cg.shared.global [%0], [%1], 16;" :: "r"(dst), "l"(src) : "memory");
}
__device__ __forceinline__ void ldm4(uint32_t* r, uint32_t addr) {
    asm volatile("ldmatrix.sync.aligned.m8n8.x4.shared.b16 {%0,%1,%2,%3}, [%4];"
                 : "=r"(r[0]), "=r"(r[1]), "=r"(r[2]), "=r"(r[3]) : "r"(addr));
}
__device__ __forceinline__ void mma_f16(float* c, const uint32_t* a, const uint32_t* b) {
    asm volatile(
        "mma.sync.aligned.m16n8k16.row.col.f32.f16.f16.f32 "
        "{%0,%1,%2,%3}, {%4,%5,%6,%7}, {%8,%9}, {%0,%1,%2,%3};"
        : "+f"(c[0]), "+f"(c[1]), "+f"(c[2]), "+f"(c[3])
        : "r"(a[0]), "r"(a[1]), "r"(a[2]), "r"(a[3]), "r"(b[0]), "r"(b[1]));
}
__device__ __forceinline__ float fsqrt_ap(float x) {
    float r; asm("sqrt.approx.f32 %0, %1;" : "=f"(r) : "f"(x)); return r;
}
__device__ __forceinline__ float fex2_ap(float x) {
    float r; asm("ex2.approx.f32 %0, %1;" : "=f"(r) : "f"(x)); return r;
}

// ---------------- warp-MMA fp16 NT GEMM (single-pass hi x hi) ----------------
// C[r,c] = sum_k A[r,k]*B[c,k]; fp16 operands, fp32 accumulate.
// CTA 128x128, 8 warps (2x4), warp tile 64x32, BK=64, double-buffered cp.async,
// single __syncthreads per chunk. Fused deterministic row partial sums.
// EPI_BIAS (DUAL): z=0/1 two merged projections; z=2 = AUX transpose slice.
// EPI_COST: v = ex2(e_r - d*cT) row-prescaled fp16 K + sum(v) partials.
// EPI_ROWS: z=0 = aligned GEMM; invrs computed IN-KERNEL from krsp (sqa arg)
//           per row block (fixed-order warp reduce -> smem). z=1 = AUX k_out
//           slice, invrs computed per 16-row block (fixed two-stage reduce).
#define EPI_ROWS 0
#define EPI_BIAS 1
#define EPI_COST 2

#define BK 64
#define ROW_BYTES 144                       // 64 halves (128B) + 16B pad
#define TILE_BYTES (128 * ROW_BYTES)        // 18432
#define SMEM_DYN (2 * 2 * TILE_BYTES + 512) // buffers + sinv[128]

template <int EPI, bool DUAL>
__global__ void __launch_bounds__(256, 2) tc_gemm(
    const __half* __restrict__ Ah, const __half* __restrict__ Bh,
    const float* __restrict__ bias,
    const __half* __restrict__ A2, const __half* __restrict__ B2,
    const float* __restrict__ bias2,
    const float* __restrict__ sqa, const float* __restrict__ sqb,
    const float* __restrict__ temp, const float* __restrict__ sbavg,
    float* __restrict__ C,
    __half* __restrict__ Chb, __half* __restrict__ Chb2,
    float* __restrict__ partial, float* __restrict__ partial2,
    const float* __restrict__ auxin, void* __restrict__ auxout,
    int N, int Kdim)
{
    extern __shared__ char dsm[];
    const int tid = threadIdx.x;

    // ---- AUX slice: transpose (proj launch, z==2) ---------------------------
    if (DUAL && blockIdx.z == 2) {
        float* tbuf = (float*)dsm;              // 32x33 tile
        __half* oh = (__half*)auxout;
        const int lx = tid & 31, ly = tid >> 5; // (32,8)
        const int base = (blockIdx.y * 8 + blockIdx.x) * 16;   // 16 tiles/block
        for (int t16 = 0; t16 < 16; t16++) {
            int tile = base + t16;              // 0..4095
            int bx = tile & 31;
            int by = tile >> 5;
            int x  = bx * 32 + lx;
            int y0 = by * 32;
#pragma unroll
            for (int i = 0; i < 4; i++)
                tbuf[(ly + i * 8) * 33 + lx] =
                    auxin[(size_t)(y0 + ly + i * 8) * DIM + x];
            __syncthreads();
            int ox  = y0 + lx;
            int oy0 = bx * 32;
#pragma unroll
            for (int i = 0; i < 4; i++) {
                float v = tbuf[lx * 33 + ly + i * 8];
                oh[(size_t)(oy0 + ly + i * 8) * NTGT + ox] = __float2half_rn(v);
            }
            __syncthreads();
        }
        return;
    }

    // ---- AUX slice: fp32 K output (aligned launch, z==1) --------------------
    // In-block deterministic invrs from krsp (sqa arg): 16 rows per block.
    if (EPI == EPI_ROWS && blockIdx.z == 1) {
        const uint2* Khs = (const uint2*)Ah;    // prescaled fp16 K
        float* Kout = (float*)auxout;
        float* pp   = (float*)dsm;              // [16][8] partials
        float* sinvk = pp + 128;                // [16]
        int bid = blockIdx.y * 8 + blockIdx.x;  // 0..255
        int row0 = bid * 16;
        if (tid < 128) {                        // t: row t/8, seg t%8 (16 each)
            int rr = tid >> 3, sg = tid & 7;
            const float* pr = sqa + (size_t)(row0 + rr) * 128 + sg * 16;
            float s = 0.f;
#pragma unroll
            for (int i = 0; i < 16; i++) s += pr[i];
            pp[rr * 8 + sg] = s;
        }
        __syncthreads();
        if (tid < 16) {                         // fixed serial order
            float s = 0.f;
#pragma unroll
            for (int i = 0; i < 8; i++) s += pp[tid * 8 + i];
            sinvk[tid] = 1.0f / s;
        }
        __syncthreads();
        size_t basei = (size_t)bid * 16384;     // uint2 units
#pragma unroll 1
        for (int i = 0; i < 64; i++) {
            size_t idx = basei + (size_t)i * 256 + tid;
            int rloc = (int)(idx >> 10) - row0;
            float inv = sinvk[rloc];
            uint2 h = Khs[idx];
            float4 v;
            v.x = __half2float(__ushort_as_half((unsigned short)(h.x & 0xffff))) * inv;
            v.y = __half2float(__ushort_as_half((unsigned short)(h.x >> 16))) * inv;
            v.z = __half2float(__ushort_as_half((unsigned short)(h.y & 0xffff))) * inv;
            v.w = __half2float(__ushort_as_half((unsigned short)(h.y >> 16))) * inv;
            ((float4*)Kout)[idx] = v;
        }
        return;
    }

    const uint32_t sm0 = smem_to_u32(dsm);
    const int wid = tid >> 5, lane = tid & 31;
    const int warpRow = wid & 1;
    const int warpCol = wid >> 1;
    const int g  = lane >> 2;
    const int qp = lane & 3;
    const int rowBase = blockIdx.y * 128;
    const int colBase = blockIdx.x * 128;

    const __half* Ause = Ah;
    const __half* Buse = Bh;
    const float*  buse = bias;
    __half* chbuse = Chb;
    float*  partuse = partial;
    if (DUAL && blockIdx.z == 1) {
        Ause = A2; Buse = B2; buse = bias2; chbuse = Chb2; partuse = partial2;
    }

    const uint32_t offA = (uint32_t)((warpRow * 64 + (lane & 7) + ((lane >> 3) & 1) * 8) * ROW_BYTES
                                     + ((lane >> 4) & 1) * 16);
    const uint32_t offB = (uint32_t)(((lane & 7) + ((lane >> 4) & 1) * 8) * ROW_BYTES
                                     + ((lane >> 3) & 1) * 16);

    const __half* basep[2] = { Ause + (size_t)rowBase * Kdim, Buse + (size_t)colBase * Kdim };

    float acc[4][4][4];
#pragma unroll
    for (int mf = 0; mf < 4; mf++)
#pragma unroll
        for (int nf = 0; nf < 4; nf++)
#pragma unroll
            for (int e = 0; e < 4; e++) acc[mf][nf][e] = 0.f;

    const int KC = Kdim / BK;

    auto issue = [&](int ch, int buf) {
        uint32_t sbase = sm0 + (uint32_t)buf * (2u * TILE_BYTES);
        int kt = ch * BK;
#pragma unroll
        for (int j = 0; j < 8; j++) {
            int id  = j * 256 + tid;
            int t   = id >> 10;
            int c   = id & 1023;
            int row = c >> 3;
            int seg = c & 7;
            const void* src = basep[t] + (size_t)row * Kdim + kt + seg * 8;
            uint32_t dst = sbase + (uint32_t)t * TILE_BYTES + row * ROW_BYTES + seg * 16;
            cp_async16(dst, src);
        }
        asm volatile("cp.async.commit_group;" ::: "memory");
    };

    issue(0, 0);
#pragma unroll 1
    for (int ch = 0; ch < KC; ch++) {
        int buf = ch & 1;
        asm volatile("cp.async.wait_group 0;" ::: "memory");
        __syncthreads();
        if (ch + 1 < KC) issue(ch + 1, buf ^ 1);

        uint32_t sb = sm0 + (uint32_t)buf * (2u * TILE_BYTES);
#pragma unroll
        for (int ks = 0; ks < 4; ks++) {
            const uint32_t kof = (uint32_t)(ks * 32);
            uint32_t bh[4][2];
#pragma unroll
            for (int p = 0; p < 2; p++) {
                uint32_t nboff = (uint32_t)((warpCol * 32 + p * 16) * ROW_BYTES);
                uint32_t rh[4];
                ldm4(rh, sb + TILE_BYTES + nboff + offB + kof);
                bh[p * 2][0] = rh[0]; bh[p * 2][1] = rh[1];
                bh[p * 2 + 1][0] = rh[2]; bh[p * 2 + 1][1] = rh[3];
            }
#pragma unroll
            for (int mf = 0; mf < 4; mf++) {
                uint32_t mof = (uint32_t)(mf * 16 * ROW_BYTES);
                uint32_t ah[4];
                ldm4(ah, sb + mof + offA + kof);
#pragma unroll
                for (int nf = 0; nf < 4; nf++) mma_f16(acc[mf][nf], ah, bh[nf]);
            }
        }
    }

    // ---- EPI_ROWS: in-kernel invrs for this row block (deterministic) -------
    float* sinv = (float*)(dsm + 4 * TILE_BYTES);
    if (EPI == EPI_ROWS) {
        // each warp: 16 rows (local wid*16 + rr), 128 partials each (krsp=sqa)
#pragma unroll 1
        for (int rr = 0; rr < 16; rr++) {
            int rloc = wid * 16 + rr;
            const float* pr = sqa + (size_t)(rowBase + rloc) * (Kdim >> 5);
            float s = 0.f;
#pragma unroll
            for (int i = 0; i < 4; i++) s += pr[lane + i * 32];
#pragma unroll
            for (int st = 16; st > 0; st >>= 1) s += __shfl_xor_sync(0xffffffffu, s, st);
            if (lane == 0) sinv[rloc] = 1.0f / s;
        }
        __syncthreads();
    }

    // ---- epilogue ------------------------------------------------------------
    const float cT = (EPI == EPI_COST) ? (1.44269504088896340736f / temp[0]) : 0.f;
    const float sbav = (EPI == EPI_COST) ? sbavg[0] : 0.f;
    const int nchunk = N >> 5;
    const int chunkIdx = (colBase >> 5) + warpCol;
#pragma unroll
    for (int mf = 0; mf < 4; mf++) {
#pragma unroll
        for (int half = 0; half < 2; half++) {
            int r = rowBase + warpRow * 64 + mf * 16 + g + half * 8;
            float sa = 0.f, er = 0.f, rowsc = 0.f;
            if (EPI == EPI_COST) {
                sa = sqa[r];
                er = rintf(fsqrt_ap(sa + sbav) * cT);
            } else if (EPI == EPI_ROWS) {
                rowsc = sinv[r - rowBase];
            }
            float rs = 0.f;
#pragma unroll
            for (int nf = 0; nf < 4; nf++) {
                int c0 = colBase + warpCol * 32 + nf * 8 + qp * 2;
                float v0 = acc[mf][nf][half * 2 + 0];
                float v1 = acc[mf][nf][half * 2 + 1];
                if (EPI == EPI_COST) {
                    float d20 = sa + sqb[c0 + 0] - 2.0f * v0;
                    float d21 = sa + sqb[c0 + 1] - 2.0f * v1;
                    v0 = fex2_ap(er - fsqrt_ap(fmaxf(d20, 0.0f)) * cT);
                    v1 = fex2_ap(er - fsqrt_ap(fmaxf(d21, 0.0f)) * cT);
                    unsigned short h0 = __half_as_ushort(__float2half_rn(v0));
                    unsigned short h1 = __half_as_ushort(__float2half_rn(v1));
                    *(uint32_t*)(chbuse + (size_t)r * N + c0) =
                        (uint32_t)h0 | ((uint32_t)h1 << 16);
                    rs += v0 + v1;
                } else if (EPI == EPI_BIAS) {
                    v0 += buse[c0 + 0];
                    v1 += buse[c0 + 1];
                    unsigned short h0 = __half_as_ushort(__float2half_rn(v0));
                    unsigned short h1 = __half_as_ushort(__float2half_rn(v1));
                    *(uint32_t*)(chbuse + (size_t)r * N + c0) =
                        (uint32_t)h0 | ((uint32_t)h1 << 16);
                    rs += v0 * v0 + v1 * v1;
                } else {   // EPI_ROWS
                    *(float2*)(C + (size_t)r * N + c0) =
                        make_float2(v0 * rowsc, v1 * rowsc);
                }
            }
            if (EPI != EPI_ROWS) {
                rs += __shfl_xor_sync(0xffffffffu, rs, 1);
                rs += __shfl_xor_sync(0xffffffffu, rs, 2);
                if (qp == 0) partuse[(size_t)r * nchunk + chunkIdx] = rs;
            }
        }
    }
}

// ---------------- small kernels ---------------------------------------------
#define N4_SRC ((size_t)NSRC * DIM / 4)
#define N4_TGT ((size_t)NTGT * DIM / 4)
#define N4_W   ((size_t)DIM * DIM / 4)
#define N4_ALL (N4_SRC + N4_TGT + 2 * N4_W)
__global__ __launch_bounds__(256) void convert_all(
    const float* __restrict__ src, const float* __restrict__ tgt,
    const float* __restrict__ ws, const float* __restrict__ wt,
    __half* __restrict__ osrc, __half* __restrict__ otgt,
    __half* __restrict__ ows, __half* __restrict__ owt)
{
    size_t i = (size_t)blockIdx.x * 256 + threadIdx.x;
    if (i >= N4_ALL) return;
    const float* in;
    __half* oh;
    size_t j = i;
    if (j < N4_SRC) { in = src; oh = osrc; }
    else if ((j -= N4_SRC) < N4_TGT) { in = tgt; oh = otgt; }
    else if ((j -= N4_TGT) < N4_W) { in = ws; oh = ows; }
    else { j -= N4_W; in = wt; oh = owt; }
    float4 v = ((const float4*)in)[j];
    unsigned short h0 = __half_as_ushort(__float2half_rn(v.x));
    unsigned short h1 = __half_as_ushort(__float2half_rn(v.y));
    unsigned short h2 = __half_as_ushort(__float2half_rn(v.z));
    unsigned short h3 = __half_as_ushort(__float2half_rn(v.w));
    ((uint2*)oh)[j] = make_uint2((uint32_t)h0 | ((uint32_t)h1 << 16),
                                 (uint32_t)h2 | ((uint32_t)h3 << 16));
}

// warp-per-row deterministic reduce (fixed shuffle tree order every run).
// Blocks 0..1023: rows (A then B). Block 1024: sbavg = sum(partB)/NTGT.
__global__ __launch_bounds__(256) void reduce_rows_warp2(
    const float* __restrict__ partA, float* __restrict__ outA,
    const float* __restrict__ partB, float* __restrict__ outB,
    float* __restrict__ avgout, int nchunk)
{
    if (blockIdx.x == (NSRC + NTGT) / 8) {   // extra block: deterministic sbavg
        __shared__ float red[256];
        const size_t total = (size_t)NTGT * nchunk;
        float s = 0.f;
        for (size_t i = threadIdx.x; i < total; i += 256) s += partB[i];
        red[threadIdx.x] = s;
        __syncthreads();
#pragma unroll
        for (int st = 128; st > 0; st >>= 1) {
            if (threadIdx.x < st) red[threadIdx.x] += red[threadIdx.x + st];
            __syncthreads();
        }
        if (threadIdx.x == 0) avgout[0] = red[0] / (float)NTGT;
        return;
    }
    int w = (int)((blockIdx.x * blockDim.x + threadIdx.x) >> 5);
    int lane = threadIdx.x & 31;
    const float* p;
    float* o;
    int r = w;
    if (w < NSRC) { p = partA; o = outA; }
    else          { p = partB; o = outB; r = w - NSRC; }
    const float* pr = p + (size_t)r * nchunk;
    float s = 0.f;
    for (int i = lane; i < nchunk; i += 32) s += pr[i];
#pragma unroll
    for (int st = 16; st > 0; st >>= 1) s += __shfl_xor_sync(0xffffffffu, s, st);
    if (lane == 0) o[r] = s;
}

// ---------------- launch -----------------------------------------------------
extern "C" void kernel_launch(void* const* d_in, const int* in_sizes, int n_in,
                              void* d_out, int out_size)
{
    const float* source = (const float*)d_in[0];
    const float* target = (const float*)d_in[1];
    const float* W_src  = (const float*)d_in[2];
    const float* b_src  = (const float*)d_in[3];
    const float* W_tgt  = (const float*)d_in[4];
    const float* b_tgt  = (const float*)d_in[5];
    const float* temp   = (const float*)d_in[6];

    float* aligned = (float*)d_out;                       // [NSRC, DIM]
    float* Kout    = (float*)d_out + (size_t)NSRC * DIM;  // [NSRC, NTGT]

    float *sqs, *sqt, *sbavg, *sqps, *sqpt, *krsp;
    __half *srch, *tgth, *Wsh, *Wth, *sph, *tph, *tTh, *Kh;
    cudaGetSymbolAddress((void**)&sqs,   g_sqs);
    cudaGetSymbolAddress((void**)&sqt,   g_sqt);
    cudaGetSymbolAddress((void**)&sbavg, g_sbavg);
    cudaGetSymbolAddress((void**)&sqps,  g_sqpart_s);
    cudaGetSymbolAddress((void**)&sqpt,  g_sqpart_t);
    cudaGetSymbolAddress((void**)&krsp,  g_krspart);
    cudaGetSymbolAddress((void**)&srch,  g_srch);
    cudaGetSymbolAddress((void**)&tgth,  g_tgth);
    cudaGetSymbolAddress((void**)&Wsh,   g_Wsh);
    cudaGetSymbolAddress((void**)&Wth,   g_Wth);
    cudaGetSymbolAddress((void**)&sph,   g_sph);
    cudaGetSymbolAddress((void**)&tph,   g_tph);
    cudaGetSymbolAddress((void**)&tTh,   g_tTh);
    cudaGetSymbolAddress((void**)&Kh,    g_Kh);

    cudaFuncSetAttribute((const void*)tc_gemm<EPI_BIAS, true>,  cudaFuncAttributeMaxDynamicSharedMemorySize, SMEM_DYN);
    cudaFuncSetAttribute((const void*)tc_gemm<EPI_COST, false>, cudaFuncAttributeMaxDynamicSharedMemorySize, SMEM_DYN);
    cudaFuncSetAttribute((const void*)tc_gemm<EPI_ROWS, false>, cudaFuncAttributeMaxDynamicSharedMemorySize, SMEM_DYN);

    // 1) convert all inputs to fp16 (single launch)
    convert_all<<<(int)((N4_ALL + 255) / 256), 256>>>(
        source, target, W_src, W_tgt, srch, tgth, Wsh, Wth);

    // 2) projections (z=0,1) + transpose slice (z=2) in ONE launch
    tc_gemm<EPI_BIAS, true><<<dim3(DIM / 128, NSRC / 128, 3), 256, SMEM_DYN>>>(
        srch, Wsh, b_src, tgth, Wth, b_tgt,
        nullptr, nullptr, nullptr, nullptr,
        nullptr, sph, tph, sqps, sqpt,
        target, tTh, DIM, DIM);

    // 3) reduce sq-norm partials + sbavg in ONE launch (extra block)
    reduce_rows_warp2<<<(NSRC + NTGT) / 8 + 1, 256>>>(
        sqps, sqs, sqpt, sqt, sbavg, DIM / 32);

    // 4) cost GEMM: row-prescaled fp16 K + scaled rowsum partials
    tc_gemm<EPI_COST, false><<<dim3(NTGT / 128, NSRC / 128), 256, SMEM_DYN>>>(
        sph, tph, nullptr, nullptr, nullptr, nullptr,
        sqs, sqt, temp, sbavg,
        nullptr, Kh, nullptr, krsp, nullptr,
        nullptr, nullptr, NTGT, DIM);

    // 5) aligned GEMM (z=0, in-kernel invrs) + fp32 K slice (z=1) in ONE launch
    tc_gemm<EPI_ROWS, false><<<dim3(DIM / 128, NSRC / 128, 2), 256, SMEM_DYN>>>(
        Kh, tTh, nullptr, nullptr, nullptr, nullptr,
        krsp, nullptr, nullptr, nullptr,
        aligned, nullptr, nullptr, nullptr, nullptr,
        nullptr, Kout, DIM, NTGT);
}